// round 14
// baseline (speedup 1.0000x reference)
#include <cuda_runtime.h>

// Appro_WAConv2d: depthwise 7x7 conv with mantissa-approximation factor.
//   term = x*w*(f1+f2-1)/(f1*f2) = u*w + s*(w/f2),  u = x/f1, s = x - u
// Packed f32x2: smem {u,s} float2, weights {w, w/f2}; one fma.rn.f32x2/tap.
// Round-14: 2-row x 4-float thread tile on FULL-plane persistent tiles.
//   Input crossbar wavefronts per output: 1.0 -> 0.625 (input LDS is the
//   dominant L1 term; weight broadcasts proven ~free in R10/R13).
//   Register layout fits occ-3: p[10] (20) + acc[8] (16) + v[10] (10).
//   Row stride 62 pairs = 496B (non-128B-multiple) rotates banks across
//   the 3 ty-rows a warp spans. Pipeline/usplit/broadcasts unchanged.

#define B_   4
#define C_   192
#define H_   56
#define W_   56
#define K_   7
#define PAD_ 3
#define SMROWS 62           // 56 + 2*3 halo rows (full plane)
#define SMC   62            // entries per row (56 + 6 halo floats)
#define NTHR  392
#define CELLS (SMROWS * SMC)  // 3844
#define NTILES (B_ * C_)    // 768 full-plane tiles
#define NBLK  456           // 152 SMs * 3 resident blocks
#define LITER 10            // ceil(CELLS / NTHR)
#define SWPAD (K_ * 8)      // 56 weight pairs (7 rows padded to 8)

// division-free split: u ~= v/f1 (signed power of 2), s = v - u.
// f1 = mantissa-map(|v|+eps) shares the mantissa of a=|v|+eps, so a/f1 is
// exactly 2^(exp(a) + topbit); dropped eps-scale term is O(1e-7).
__device__ __forceinline__ float2 usplit(float v) {
    float a = fabsf(v) + 1e-7f;
    unsigned ab = __float_as_uint(a);
    unsigned ub = (__float_as_uint(v) & 0x80000000u)
                | ((ab & 0x7F800000u) + ((ab & 0x00400000u) << 1));
    float u = __uint_as_float(ub);
    return make_float2(u, v - u);
}

__device__ __forceinline__ unsigned long long fma2(unsigned long long a,
                                                   unsigned long long b,
                                                   unsigned long long c) {
    unsigned long long d;
    asm("fma.rn.f32x2 %0, %1, %2, %3;" : "=l"(d) : "l"(a), "l"(b), "l"(c));
    return d;
}

__device__ __forceinline__ float pairsum(unsigned long long v) {
    return __uint_as_float((unsigned)v) + __uint_as_float((unsigned)(v >> 32));
}

// dynamic smem: sm[2][CELLS] float2, then sw[2][SWPAD] float2
extern __shared__ __align__(16) float2 dynsm[];

__global__ __launch_bounds__(NTHR, 3)
void waconv_kernel(const float* __restrict__ x,
                   const float* __restrict__ w,
                   float* __restrict__ out) {
    float2* const sm0 = dynsm;
    float2* const sm1 = dynsm + CELLS;
    float2* const sw0 = dynsm + 2 * CELLS;
    float2* const sw1 = sw0 + SWPAD;

    const int tid = threadIdx.x;
    const int t0 = (int)(((long long)blockIdx.x       * NTILES) / NBLK);
    const int t1 = (int)(((long long)(blockIdx.x + 1) * NTILES) / NBLK);

    const int ty = tid / 14;               // 0..27
    const int tx = tid - ty * 14;          // 0..13
    const int y0 = ty * 2;                 // output rows y0, y0+1
    const int x0 = tx * 4;                 // output floats x0..x0+3

    // ---- prologue: fill buffer 0 with plane t0 (direct, stalls once) ----
    {
        const float* __restrict__ xp = x + (size_t)t0 * (H_ * W_);
        if (tid < SWPAD) {
            int j = tid & 7;
            float2 v2 = make_float2(0.0f, 0.0f);
            if (j < K_) {
                float wv = w[(t0 % C_) * (K_ * K_) + (tid >> 3) * K_ + j];
                v2 = make_float2(wv, usplit(wv).x);   // {w, ~w/f2}
            }
            sw0[tid] = v2;
        }
#pragma unroll
        for (int kk = 0; kk < LITER; ++kk) {
            int idx = tid + kk * NTHR;
            if (idx < CELLS) {
                int r = idx / SMC, q = idx - r * SMC;
                int iy = r - PAD_, ix = q - PAD_;
                float v = 0.0f;
                if ((unsigned)iy < H_ && (unsigned)ix < W_) v = xp[iy * W_ + ix];
                sm0[idx] = usplit(v);
            }
        }
    }
    __syncthreads();

    // ---- persistent tile loop ----
    for (int k = t0; k < t1; ++k) {
        const int buf = (k - t0) & 1;
        const float2* __restrict__ smb = buf ? sm1 : sm0;
        const ulonglong2* __restrict__ swq =
            (const ulonglong2*)(buf ? sw1 : sw0);
        float2* const smn = buf ? sm0 : sm1;
        float2* const swn = buf ? sw0 : sw1;
        const bool more = (k + 1 < t1);

        // stage A: issue next plane's global loads (independent LDGs)
        float v[LITER];
        if (more) {
            const float* __restrict__ xp = x + (size_t)(k + 1) * (H_ * W_);
#pragma unroll
            for (int kk = 0; kk < LITER; ++kk) {
                int idx = tid + kk * NTHR;
                float vv = 0.0f;
                if (idx < CELLS) {
                    int r = idx / SMC, q = idx - r * SMC;
                    int iy = r - PAD_, ix = q - PAD_;
                    if ((unsigned)iy < H_ && (unsigned)ix < W_)
                        vv = __ldg(xp + iy * W_ + ix);
                }
                v[kk] = vv;
            }
        }

        // stage B: compute 2x4 tile from smb
        {
            unsigned long long acc[2][4];
#pragma unroll
            for (int m = 0; m < 4; ++m) { acc[0][m] = 0ull; acc[1][m] = 0ull; }

#pragma unroll
            for (int t = 0; t < 8; ++t) {        // input row = y0 + t
                const unsigned long long* pr =
                    (const unsigned long long*)&smb[(y0 + t) * SMC + x0];
                unsigned long long p[10];        // entries x0 .. x0+9
                ((ulonglong2*)p)[0] = ((const ulonglong2*)pr)[0];
                ((ulonglong2*)p)[1] = ((const ulonglong2*)pr)[1];
                ((ulonglong2*)p)[2] = ((const ulonglong2*)pr)[2];
                ((ulonglong2*)p)[3] = ((const ulonglong2*)pr)[3];
                ((ulonglong2*)p)[4] = ((const ulonglong2*)pr)[4];

                // oy = 0 uses kernel row i = t (valid t<=6)
                if (t <= 6) {
#pragma unroll
                    for (int jj = 0; jj < 4; ++jj) {
                        ulonglong2 wp = swq[(t << 2) + jj];  // LDS.128 bcast
                        const int j0 = 2 * jj;
#pragma unroll
                        for (int m = 0; m < 4; ++m)
                            acc[0][m] = fma2(p[m + j0], wp.x, acc[0][m]);
                        if (j0 + 1 < K_) {
#pragma unroll
                            for (int m = 0; m < 4; ++m)
                                acc[0][m] = fma2(p[m + j0 + 1], wp.y, acc[0][m]);
                        }
                    }
                }
                // oy = 1 uses kernel row i = t-1 (valid t>=1)
                if (t >= 1) {
#pragma unroll
                    for (int jj = 0; jj < 4; ++jj) {
                        ulonglong2 wp = swq[((t - 1) << 2) + jj];
                        const int j0 = 2 * jj;
#pragma unroll
                        for (int m = 0; m < 4; ++m)
                            acc[1][m] = fma2(p[m + j0], wp.x, acc[1][m]);
                        if (j0 + 1 < K_) {
#pragma unroll
                            for (int m = 0; m < 4; ++m)
                                acc[1][m] = fma2(p[m + j0 + 1], wp.y, acc[1][m]);
                        }
                    }
                }
            }
            float* op = out + (size_t)k * (H_ * W_) + y0 * W_ + x0;
            *(float4*)(op) = make_float4(pairsum(acc[0][0]), pairsum(acc[0][1]),
                                         pairsum(acc[0][2]), pairsum(acc[0][3]));
            *(float4*)(op + W_) =
                make_float4(pairsum(acc[1][0]), pairsum(acc[1][1]),
                            pairsum(acc[1][2]), pairsum(acc[1][3]));
        }

        // stage C: split staged regs into the other buffer + next weights
        if (more) {
            if (tid < SWPAD) {
                int j = tid & 7;
                float2 v2 = make_float2(0.0f, 0.0f);
                if (j < K_) {
                    float wv = w[((k + 1) % C_) * (K_ * K_) + (tid >> 3) * K_ + j];
                    v2 = make_float2(wv, usplit(wv).x);
                }
                swn[tid] = v2;
            }
#pragma unroll
            for (int kk = 0; kk < LITER; ++kk) {
                int idx = tid + kk * NTHR;
                if (idx < CELLS) smn[idx] = usplit(v[kk]);
            }
        }
        __syncthreads();
    }
}

#define SMEM_BYTES ((2 * CELLS + 2 * SWPAD) * (int)sizeof(float2))

extern "C" void kernel_launch(void* const* d_in, const int* in_sizes, int n_in,
                              void* d_out, int out_size) {
    const float* x  = (const float*)d_in[0];   // (4,192,56,56) f32
    const float* wt = (const float*)d_in[1];   // (192,1,7,7)  f32
    float* out = (float*)d_out;                // (4,192,56,56) f32
    (void)in_sizes; (void)n_in; (void)out_size;
    static int configured = 0;
    if (!configured) {
        cudaFuncSetAttribute(waconv_kernel,
                             cudaFuncAttributeMaxDynamicSharedMemorySize,
                             SMEM_BYTES);
        configured = 1;
    }
    waconv_kernel<<<NBLK, NTHR, SMEM_BYTES>>>(x, wt, out);
}

// round 15
// speedup vs baseline: 1.1706x; 1.1706x over previous
#include <cuda_runtime.h>

// Appro_WAConv2d: depthwise 7x7 conv with mantissa-approximation factor.
//   term = x*w*(f1+f2-1)/(f1*f2) = u*w + s*(w/f2),  u = x/f1, s = x - u
// Packed f32x2: smem {u,s} float2, weights {w, w/f2}; one fma.rn.f32x2/tap.
// Round-15: R10/R13 body unchanged (proven local optimum at 48 regs /
// occ-3). Change the SCHEDULE: static 3-or-4-tile split (19% tail waste,
// 1536 tiles / 456 blocks) -> global atomic work-stealing counter, one
// tile lookahead so the A/B/C pipeline still prefetches tile n+1 while
// computing tile n. Counter reset by a tiny kernel in the same graph.

#define B_   4
#define C_   192
#define H_   56
#define W_   56
#define K_   7
#define PAD_ 3
#define HR    28            // output rows per tile (half plane)
#define SMROWS 34           // 28 + 2*3 halo rows
#define SR    64            // smem row stride in float2 (pow2 indexing)
#define NTHR  392
#define CELLS (SMROWS * SR) // 2176
#define NTILES (B_ * C_ * 2)  // 1536
#define NBLK  456           // 152 SMs * 3 resident blocks (one full wave)

__device__ unsigned int g_tile_ctr;

__global__ void reset_ctr_kernel() { g_tile_ctr = 0u; }

// division-free split: u ~= v/f1 (signed power of 2), s = v - u.
// f1 = mantissa-map(|v|+eps) shares the mantissa of a=|v|+eps, so a/f1 is
// exactly 2^(exp(a) + topbit); dropped eps-scale term is O(1e-7).
__device__ __forceinline__ float2 usplit(float v) {
    float a = fabsf(v) + 1e-7f;
    unsigned ab = __float_as_uint(a);
    unsigned ub = (__float_as_uint(v) & 0x80000000u)
                | ((ab & 0x7F800000u) + ((ab & 0x00400000u) << 1));
    float u = __uint_as_float(ub);
    return make_float2(u, v - u);
}

__device__ __forceinline__ unsigned long long fma2(unsigned long long a,
                                                   unsigned long long b,
                                                   unsigned long long c) {
    unsigned long long d;
    asm("fma.rn.f32x2 %0, %1, %2, %3;" : "=l"(d) : "l"(a), "l"(b), "l"(c));
    return d;
}

__device__ __forceinline__ float pairsum(unsigned long long v) {
    return __uint_as_float((unsigned)v) + __uint_as_float((unsigned)(v >> 32));
}

__global__ __launch_bounds__(NTHR, 3)
void waconv_kernel(const float* __restrict__ x,
                   const float* __restrict__ w,
                   float* __restrict__ out) {
    __shared__ __align__(16) float2 sm[2][CELLS];     // {u, s} interleaved
    __shared__ __align__(16) float2 sw[2][K_ * 8];    // {w, w/f2}, rows of 8
    __shared__ int sh_cur;
    __shared__ int sh_next[2];

    const int tid = threadIdx.x;
    const int ty = tid / 28;               // 0..13
    const int tx = tid - ty * 28;          // 0..27
    const int y0 = ty * 2;
    const int x0 = tx * 2;

    // ---- grab first two tiles ----
    if (tid == 0) {
        sh_cur     = (int)atomicAdd(&g_tile_ctr, 1u);
        sh_next[0] = (int)atomicAdd(&g_tile_ctr, 1u);
    }
    __syncthreads();
    int cur = sh_cur;
    if (cur >= NTILES) return;             // uniform across block

    // ---- prologue: fill buffer 0 with tile cur ----
    {
        const int plane = cur >> 1;
        const int h0 = (cur & 1) * HR;
        const float* __restrict__ xp = x + (size_t)plane * (H_ * W_);
        if (tid < K_ * 8) {
            int j = tid & 7;
            float2 v2 = make_float2(0.0f, 0.0f);
            if (j < K_) {
                float wv = w[(plane % C_) * (K_ * K_) + (tid >> 3) * K_ + j];
                v2 = make_float2(wv, usplit(wv).x);   // {w, ~w/f2}
            }
            sw[0][tid] = v2;
        }
#pragma unroll
        for (int kk = 0; kk < 6; ++kk) {
            int idx = tid + kk * NTHR;
            if (idx < CELLS) {
                int r = idx >> 6, q = idx & 63;
                int iy = h0 + r - PAD_, ix = q - PAD_;
                float v = 0.0f;
                if ((unsigned)iy < H_ && (unsigned)ix < W_) v = xp[iy * W_ + ix];
                sm[0][idx] = usplit(v);
            }
        }
    }
    __syncthreads();

    // ---- persistent tile loop (work-stealing, one tile lookahead) ----
    int it = 0;
    while (cur < NTILES) {
        const int nxt = sh_next[it & 1];   // written last iter (or prologue)
        const int buf = it & 1;
        const bool more = (nxt < NTILES);
        const int plane = cur >> 1;
        const int h0 = (cur & 1) * HR;

        // stage A: issue next tile's global loads (6 independent LDGs)
        float v[6];
        int nplane = 0;
        if (more) {
            nplane = nxt >> 1;
            const int nh0 = (nxt & 1) * HR;
            const float* __restrict__ xp = x + (size_t)nplane * (H_ * W_);
#pragma unroll
            for (int kk = 0; kk < 6; ++kk) {
                int idx = tid + kk * NTHR;
                float vv = 0.0f;
                if (idx < CELLS) {
                    int r = idx >> 6, q = idx & 63;
                    int iy = nh0 + r - PAD_, ix = q - PAD_;
                    if ((unsigned)iy < H_ && (unsigned)ix < W_)
                        vv = __ldg(xp + iy * W_ + ix);
                }
                v[kk] = vv;
            }
        }

        // stage B: compute current tile from sm[buf]
        {
            const ulonglong2* __restrict__ swq = (const ulonglong2*)sw[buf];
            const float2* __restrict__ smb = sm[buf];
            unsigned long long acc00 = 0ull, acc01 = 0ull,
                               acc10 = 0ull, acc11 = 0ull;
#pragma unroll
            for (int t = 0; t < 8; ++t) {
                const unsigned long long* pr =
                    (const unsigned long long*)&smb[((y0 + t) << 6) + x0];
                unsigned long long p[8];
                ((ulonglong2*)p)[0] = ((const ulonglong2*)pr)[0];
                ((ulonglong2*)p)[1] = ((const ulonglong2*)pr)[1];
                ((ulonglong2*)p)[2] = ((const ulonglong2*)pr)[2];
                ((ulonglong2*)p)[3] = ((const ulonglong2*)pr)[3];

                // oy = 0 uses kernel row i = t (valid t<=6)
                if (t <= 6) {
#pragma unroll
                    for (int jj = 0; jj < 4; ++jj) {       // j = 2jj, 2jj+1
                        ulonglong2 wp = swq[(t << 2) + jj]; // LDS.128 bcast
                        const int j0 = 2 * jj;
                        acc00 = fma2(p[j0],     wp.x, acc00);
                        acc01 = fma2(p[j0 + 1], wp.x, acc01);
                        if (j0 + 1 < K_) {
                            acc00 = fma2(p[j0 + 1], wp.y, acc00);
                            acc01 = fma2(p[j0 + 2], wp.y, acc01);
                        }
                    }
                }
                // oy = 1 uses kernel row i = t-1 (valid t>=1)
                if (t >= 1) {
#pragma unroll
                    for (int jj = 0; jj < 4; ++jj) {
                        ulonglong2 wp = swq[((t - 1) << 2) + jj];
                        const int j0 = 2 * jj;
                        acc10 = fma2(p[j0],     wp.x, acc10);
                        acc11 = fma2(p[j0 + 1], wp.x, acc11);
                        if (j0 + 1 < K_) {
                            acc10 = fma2(p[j0 + 1], wp.y, acc10);
                            acc11 = fma2(p[j0 + 2], wp.y, acc11);
                        }
                    }
                }
            }
            float* op = out + (size_t)plane * (H_ * W_) + (h0 + y0) * W_ + x0;
            *(float2*)(op)      = make_float2(pairsum(acc00), pairsum(acc01));
            *(float2*)(op + W_) = make_float2(pairsum(acc10), pairsum(acc11));
        }

        // grab the tile after next (visible to all after the barrier below)
        if (tid == 0)
            sh_next[(it + 1) & 1] = (int)atomicAdd(&g_tile_ctr, 1u);

        // stage C: split staged regs into sm[buf^1], next weights
        if (more) {
            if (tid < K_ * 8) {
                int j = tid & 7;
                float2 v2 = make_float2(0.0f, 0.0f);
                if (j < K_) {
                    float wv = w[(nplane % C_) * (K_ * K_) + (tid >> 3) * K_ + j];
                    v2 = make_float2(wv, usplit(wv).x);
                }
                sw[buf ^ 1][tid] = v2;
            }
#pragma unroll
            for (int kk = 0; kk < 6; ++kk) {
                int idx = tid + kk * NTHR;
                if (idx < CELLS) sm[buf ^ 1][idx] = usplit(v[kk]);
            }
        }
        __syncthreads();
        cur = nxt;
        ++it;
    }
}

extern "C" void kernel_launch(void* const* d_in, const int* in_sizes, int n_in,
                              void* d_out, int out_size) {
    const float* x  = (const float*)d_in[0];   // (4,192,56,56) f32
    const float* wt = (const float*)d_in[1];   // (192,1,7,7)  f32
    float* out = (float*)d_out;                // (4,192,56,56) f32
    (void)in_sizes; (void)n_in; (void)out_size;
    reset_ctr_kernel<<<1, 1>>>();
    waconv_kernel<<<NBLK, NTHR>>>(x, wt, out);
}